// round 14
// baseline (speedup 1.0000x reference)
#include <cuda_runtime.h>
#include <cuda_bf16.h>
#include <cstdint>

#define NB    256
#define NC    512
#define NHW   81
#define NFLAT (NC*NHW)           // 41472 per batch
#define EPSV  1e-5f

__device__ __forceinline__ float to_tf32(float x) {
    float r; asm("cvt.rna.tf32.f32 %0, %1;" : "=f"(r) : "f"(x)); return r;
}
// m16n8k8 tf32 warp MMA (baseline PTX, sm_80+): D += A*B
__device__ __forceinline__ void mma_tf32(float c[4],
                                         uint32_t a0, uint32_t a1,
                                         uint32_t a2, uint32_t a3,
                                         uint32_t b0, uint32_t b1) {
    asm volatile("mma.sync.aligned.m16n8k8.row.col.f32.tf32.tf32.f32 "
                 "{%0,%1,%2,%3}, {%4,%5,%6,%7}, {%8,%9}, {%0,%1,%2,%3};"
                 : "+f"(c[0]), "+f"(c[1]), "+f"(c[2]), "+f"(c[3])
                 : "r"(a0), "r"(a1), "r"(a2), "r"(a3), "r"(b0), "r"(b1));
}
__device__ __forceinline__ void cp_async16(uint32_t s, const void* g) {
    asm volatile("cp.async.ca.shared.global [%0], [%1], 16;" :: "r"(s), "l"(g));
}
__device__ __forceinline__ void cp_commit() {
    asm volatile("cp.async.commit_group;");
}
template<int N>
__device__ __forceinline__ void cp_wait() {
    asm volatile("cp.async.wait_group %0;" :: "n"(N));
}

// Global scratch (allocation-free rule: __device__ arrays)
__device__ __align__(16) float g_k1[(size_t)NB * NFLAT];  // SeMCA key
__device__ __align__(16) float g_v [(size_t)NB * NFLAT];  // SeMCA value (dw3x3)

// ---------------------------------------------------------------------------
// Kernel A (banded, register-held k1/k1s): grid = NB*8. Each CTA: one batch x
// one 64-channel band (+4 halo). 8 warps = 8 heads. k1 and k1s are written
// and read by the SAME thread at the SAME pixel indices -> held in registers
// (ksr/k1r [8][3]); the 41KB smem stage is gone. All per-channel params incl.
// att_w1 staged into smem P (coalesced; broadcast LDS in the inner loops).
// smem floats: Xs[5832] | sekw[729] | sekb[81] | P[64*40]  = 9202 fl = 36.8KB
// ---------------------------------------------------------------------------
#define A_SMEM_FLOATS (5832 + 729 + 81 + 64*40)   // 9202

__global__ __launch_bounds__(256, 3)
void dmuca_kernelA(const float* __restrict__ x,
                   const float* __restrict__ alpha_p,
                   const float* __restrict__ sa_key_w,
                   const float* __restrict__ sa_key_bn,
                   const float* __restrict__ sa_att_w1,
                   const float* __restrict__ sa_att_bn,
                   const float* __restrict__ sa_att_w2,
                   const float* __restrict__ sa_att_b2,
                   const float* __restrict__ se_key_w,
                   const float* __restrict__ se_key_b,
                   const float* __restrict__ se_val_w,
                   const float* __restrict__ se_val_b,
                   float* __restrict__ out)
{
    extern __shared__ float sm[];
    float* Xs    = sm;                    // 5832 (72 rows x 81)
    float* sekw  = sm + 5832;             // 729
    float* sekb  = sekw + 729;            // 81
    float* P     = sekb + 81;             // 64 ch * 40

    const int bb   = blockIdx.x;
    const int b    = bb >> 3;
    const int band = bb & 7;
    const int chlo = band << 6;
    const int tid  = threadIdx.x;
    const int warp = tid >> 5;
    const int lane = tid & 31;
    const float* xb = x + (size_t)b * NFLAT;

    // ---- staging ----
    {
        const int gbase = (chlo - 4) * NHW;
        for (int i = tid; i < 5832; i += 256) {
            const int g = gbase + i;
            Xs[i] = ((unsigned)g < (unsigned)NFLAT) ? xb[g] : 0.f;
        }
        for (int i = tid; i < 729; i += 256) sekw[i] = se_key_w[i];
        if (tid < 81) sekb[tid] = se_key_b[tid];

        // P per local channel c (stride 40): [0..8] val_w, [9..17] key_w,
        // [18..33] att_w1, [34] val_b, [35] keyS, [36] keyH,
        // [37] attS, [38] attH, [39] att_w2
        for (int i = tid; i < 576; i += 256) {        // val_w
            const int c = i / 9, k = i - c * 9;
            P[c*40 + k] = se_val_w[(chlo + c)*9 + k];
        }
        for (int i = tid; i < 576; i += 256) {        // key_w
            const int c = i / 9, k = i - c * 9;
            P[c*40 + 9 + k] = sa_key_w[(chlo + c)*9 + k];
        }
        for (int i = tid; i < 1024; i += 256) {       // att_w1
            const int c = i >> 4, k = i & 15;
            P[c*40 + 18 + k] = sa_att_w1[(chlo + c)*16 + k];
        }
        if (tid < 64) {
            const int ch = chlo + tid;
            float* Pc = P + tid*40;
            Pc[34] = se_val_b[ch];
            const float s1 = sa_key_bn[ch] * rsqrtf(sa_key_bn[1536 + ch] + EPSV);
            Pc[35] = s1;
            Pc[36] = sa_key_bn[512 + ch] - sa_key_bn[1024 + ch] * s1;
            const float s2 = sa_att_bn[ch] * rsqrtf(sa_att_bn[1536 + ch] + EPSV);
            Pc[37] = s2;
            Pc[38] = sa_att_bn[512 + ch] - sa_att_bn[1024 + ch] * s2;
            Pc[39] = sa_att_w2[ch];
        }
    }
    __syncthreads();

    const float alpha = alpha_p[0];
    const float oma   = 1.0f - alpha;

    const int g_head = (chlo >> 3) + warp;
    const int chbase = chlo + warp * 8;

    float ksr[8][3];   // k1s (relu(bn(dw3x3))) for this thread's 8ch x 3px
    float k1r[8][3];   // k1 (spectral 9-tap) same

    // ---- Part 1: k1, v -> global; k1s, k1 -> registers ----------------------
    #pragma unroll
    for (int l = 0; l < 8; l++) {
        const int ch = chbase + l;
        const int lc = warp*8 + l;
        const int lr = lc + 4;
        const float* Xc = Xs + lr * NHW;
        const float* Pc = P + lc * 40;

        float wkv[9], wks[9];
        #pragma unroll
        for (int k = 0; k < 9; k++) wkv[k] = Pc[k];
        #pragma unroll
        for (int k = 0; k < 9; k++) wks[k] = Pc[9 + k];
        const float vbias = Pc[34];
        const float s  = Pc[35];
        const float sh = Pc[36];

        float* gk = g_k1 + (size_t)b * NFLAT + ch * NHW;
        float* gv = g_v  + (size_t)b * NFLAT + ch * NHW;

        #pragma unroll
        for (int t = 0; t < 3; t++) {
            const int p = lane + 32 * t;
            if (p < 81) {
                float acc = sekb[p];
                #pragma unroll
                for (int d = 0; d < 9; d++)
                    acc = fmaf(sekw[p*9 + d], Xs[(lr - 4 + d)*NHW + p], acc);
                gk[p] = acc;
                k1r[l][t] = acc;

                const int h = p / 9, w = p - h * 9;
                float va = vbias, sa = 0.f;
                #pragma unroll
                for (int kh = 0; kh < 3; kh++) {
                    const int hh = h + kh - 1;
                    if ((unsigned)hh < 9u) {
                        #pragma unroll
                        for (int kw = 0; kw < 3; kw++) {
                            const int ww = w + kw - 1;
                            if ((unsigned)ww < 9u) {
                                const float xv = Xc[hh*9 + ww];
                                va = fmaf(wkv[kh*3+kw], xv, va);
                                sa = fmaf(wks[kh*3+kw], xv, sa);
                            }
                        }
                    }
                }
                gv[p] = va;
                ksr[l][t] = fmaxf(fmaf(sa, s, sh), 0.f);
            } else {
                k1r[l][t] = 0.f;
                ksr[l][t] = 0.f;
            }
        }
    }

    // ---- Part 2: head attention logits (all operands thread-local/smem) ----
    const float bg = __ldg(sa_att_b2 + g_head);
    float a2b[3] = {bg, bg, bg};
    #pragma unroll
    for (int o = 0; o < 8; o++) {
        const float* Pc = P + (warp*8 + o) * 40;
        float w1r[16];
        #pragma unroll
        for (int i = 0; i < 16; i++) w1r[i] = Pc[18 + i];
        const float s2  = Pc[37];
        const float sh2 = Pc[38];
        const float w2v = Pc[39];
        #pragma unroll
        for (int t = 0; t < 3; t++) {
            const int pp = lane + 32 * t;
            if (pp < 81) {
                float aa = 0.f;
                #pragma unroll
                for (int l = 0; l < 8; l++) {
                    aa = fmaf(w1r[2*l],   ksr[l][t], aa);
                    aa = fmaf(w1r[2*l+1], Xs[(warp*8 + l + 4)*NHW + pp], aa);
                }
                aa = fmaxf(fmaf(aa, s2, sh2), 0.f);
                a2b[t] = fmaf(w2v, aa, a2b[t]);
            }
        }
    }

    // ---- warp softmax over 81 pixels ---------------------------------------
    float m = -1e30f;
    #pragma unroll
    for (int t = 0; t < 3; t++) { if (lane + 32*t < 81) m = fmaxf(m, a2b[t]); }
    #pragma unroll
    for (int off = 16; off > 0; off >>= 1)
        m = fmaxf(m, __shfl_xor_sync(0xffffffffu, m, off));
    float ex[3] = {0.f, 0.f, 0.f};
    float ssum = 0.f;
    #pragma unroll
    for (int t = 0; t < 3; t++) {
        const int pp = lane + 32 * t;
        if (pp < 81) { ex[t] = __expf(a2b[t] - m); ssum += ex[t]; }
    }
    #pragma unroll
    for (int off = 16; off > 0; off >>= 1)
        ssum += __shfl_xor_sync(0xffffffffu, ssum, off);
    const float inv = 1.0f / ssum;

    // ---- out = (1-a)*(k1s + attn*x) + a*k1  (k1s/k1 from registers) ---------
    #pragma unroll
    for (int t = 0; t < 3; t++) {
        const int pp = lane + 32 * t;
        if (pp < 81) {
            const float att = ex[t] * inv;
            #pragma unroll
            for (int l = 0; l < 8; l++) {
                const int ch = chbase + l;
                const float o2 = ksr[l][t]
                               + att * Xs[(warp*8 + l + 4)*NHW + pp];
                out[(size_t)b * NFLAT + ch*NHW + pp]
                    = oma * o2 + alpha * k1r[l][t];
            }
        }
    }
}

// ---------------------------------------------------------------------------
// Kernel B (warp-MMA tf32): round-13 + one-barrier-per-chunk reorder (issue
// next stage AFTER the top-of-loop wait+sync; the single sync covers both the
// data-arrival and the WAR hazard on the refilled buffer). v-band staging
// still overlapped with the pass-1 epilogue (extra sync guards the alias).
// ---------------------------------------------------------------------------
#define FB_SH   0
#define FB_W1F  16640
#define FB_A2S  42120
#define FB_W2   46728
#define FB_BNS  47457
#define FB_BNH  47538
#define B_SMEM_FLOATS 47619
#define SH_STRIDE 520

__global__ __launch_bounds__(512, 1)
void dmuca_kernelB(const float* __restrict__ x,
                   const float* __restrict__ alpha_p,
                   const float* __restrict__ se_att_w1,
                   const float* __restrict__ se_att_bn,
                   const float* __restrict__ se_att_w2,
                   const float* __restrict__ se_att_b2,
                   float* __restrict__ out)
{
    extern __shared__ float sm[];
    float* SH2 = sm + FB_SH;    // 2 x [16][520] raw f32 chunks of S
    float* W1f = sm + FB_W1F;   // [j=176][o pad 104] tf32
    float* vsm = sm;            // epilogue alias, 520*81 = 42120
    float* a2s = sm + FB_A2S;
    float* w2s = sm + FB_W2;
    float* bnS = sm + FB_BNS;
    float* bnH = sm + FB_BNH;

    const int b    = blockIdx.x;
    const int tid  = threadIdx.x;
    const int warp = tid >> 5;
    const int lane = tid & 31;
    const int gid  = lane >> 2;       // 0..7
    const int tig  = lane & 3;        // 0..3
    const float* xb  = x    + (size_t)b * NFLAT;
    const float* k1b = g_k1 + (size_t)b * NFLAT;

    const uint32_t sh_base  = (uint32_t)__cvta_generic_to_shared(SH2);
    const uint32_t vsm_base = (uint32_t)__cvta_generic_to_shared(vsm);

    // one-time staging: W1f (tf32, zero-padded), w2s, bn scale/shift
    for (int i = tid; i < 176*104; i += 512) {
        const int k = i / 104, o = i - k * 104;
        const float w = (o < 81 && k < 162) ? __ldg(se_att_w1 + o*162 + k) : 0.f;
        W1f[i] = to_tf32(w);
    }
    for (int i = tid; i < 729; i += 512) w2s[i] = se_att_w2[i];
    if (tid < 81) {
        const float gam = se_att_bn[tid],       bet = se_att_bn[81 + tid];
        const float mea = se_att_bn[162 + tid], var = se_att_bn[243 + tid];
        const float s = gam * rsqrtf(var + EPSV);
        bnS[tid] = s; bnH[tid] = bet - mea * s;
    }

    // stage chunk c (k rows c*16..c*16+15) into buffer `buf` via cp.async
    auto stage_chunk = [&](int c, int buf) {
        const uint32_t boff = (uint32_t)(buf * 16 * SH_STRIDE * 4);
        #pragma unroll
        for (int q = 0; q < 4; q++) {
            const int f4 = q * 512 + tid;          // 0..2047
            const int kk = f4 >> 7, c4 = f4 & 127; // 128 float4 per 512-f row
            const int j  = c * 16 + kk;
            const uint32_t dst = sh_base + boff
                               + (uint32_t)((kk * SH_STRIDE + c4 * 4) * 4);
            if (j < 81) {
                cp_async16(dst, (const void*)(xb + j*512 + c4*4));
            } else if (j < 162) {
                cp_async16(dst, (const void*)(k1b + (j-81)*512 + c4*4));
            } else {
                float4 z = {0.f, 0.f, 0.f, 0.f};
                *(float4*)(SH2 + buf*16*SH_STRIDE + kk*SH_STRIDE + c4*4) = z;
            }
        }
        cp_commit();
    };

    stage_chunk(0, 0);

    for (int pass = 0; pass < 2; pass++) {
        const int m0 = (warp + 16 * pass) << 4;    // channel base

        float acc[11][4];
        #pragma unroll
        for (int nb = 0; nb < 11; nb++)
            #pragma unroll
            for (int e = 0; e < 4; e++) acc[nb][e] = 0.f;

        for (int kc = 0; kc < 11; kc++) {
            const int gi = pass * 11 + kc;
            cp_wait<0>();            // chunk gi has landed
            __syncthreads();         // + all compute of chunk gi-1 done
            if (gi < 21) stage_chunk((gi + 1) % 11, (gi + 1) & 1);

            const float* sb = SH2 + (gi & 1) * 16 * SH_STRIDE;
            #pragma unroll
            for (int ks = 0; ks < 2; ks++) {
                const int kl = ks * 8 + tig;
                const int jr = kc * 16 + kl;
                const uint32_t a0 = __float_as_uint(sb[ kl     *SH_STRIDE + m0 + gid]);
                const uint32_t a1 = __float_as_uint(sb[ kl     *SH_STRIDE + m0 + gid + 8]);
                const uint32_t a2 = __float_as_uint(sb[(kl + 4)*SH_STRIDE + m0 + gid]);
                const uint32_t a3 = __float_as_uint(sb[(kl + 4)*SH_STRIDE + m0 + gid + 8]);
                const float* wr0 = W1f + (size_t)jr * 104;
                const float* wr1 = W1f + (size_t)(jr + 4) * 104;
                #pragma unroll
                for (int nb = 0; nb < 11; nb++) {
                    const uint32_t b0 = __float_as_uint(wr0[nb*8 + gid]);
                    const uint32_t b1 = __float_as_uint(wr1[nb*8 + gid]);
                    mma_tf32(acc[nb], a0, a1, a2, a3, b0, b1);
                }
            }
        }

        // After the FINAL mainloop chunk SH2/W1f are dead: overlap the v-band
        // staging (cp.async into the alias region) with the register epilogue
        // and softmax. Sync first: other warps must finish the last chunk.
        if (pass == 1) {
            __syncthreads();
            const float* vb = g_v + (size_t)b * NFLAT;
            // zero edges: rows 0..3 (first 324 floats) and 516..519 (last 324)
            for (int i = tid; i < 324; i += 512) {
                vsm[i] = 0.f;
                vsm[41796 + i] = 0.f;   // 516*81 = 41796
            }
            // interior: channels 0..511 -> vsm offset 324 + ch*81
            #pragma unroll
            for (int q = 0; q < 21; q++) {
                const int f4 = q * 512 + tid;       // float4 index
                if (f4 < 10368) {                   // 41472/4
                    cp_async16(vsm_base + (uint32_t)((324 + f4*4) * 4),
                               (const void*)(vb + f4*4));
                }
            }
            cp_commit();
        }

        // register epilogue: bn+relu+w2 -> logits for channels m0+gid, m0+gid+8
        float lg[2][9];
        #pragma unroll
        for (int rr = 0; rr < 2; rr++)
            #pragma unroll
            for (int d = 0; d < 9; d++) lg[rr][d] = 0.f;
        #pragma unroll
        for (int nb = 0; nb < 11; nb++) {
            #pragma unroll
            for (int e = 0; e < 4; e++) {
                const int o = nb*8 + tig*2 + (e & 1);
                if (o < 81) {
                    const float a1v = fmaxf(fmaf(acc[nb][e], bnS[o], bnH[o]), 0.f);
                    const int rr = e >> 1;
                    #pragma unroll
                    for (int d = 0; d < 9; d++)
                        lg[rr][d] = fmaf(w2s[d*81 + o], a1v, lg[rr][d]);
                }
            }
        }
        #pragma unroll
        for (int rr = 0; rr < 2; rr++)
            #pragma unroll
            for (int d = 0; d < 9; d++) {
                lg[rr][d] += __shfl_xor_sync(0xffffffffu, lg[rr][d], 1);
                lg[rr][d] += __shfl_xor_sync(0xffffffffu, lg[rr][d], 2);
            }
        if (tig == 0) {
            #pragma unroll
            for (int d = 0; d < 9; d++) {
                const float bias = __ldg(se_att_b2 + d);
                a2s[d*512 + m0 + gid]     = lg[0][d] + bias;
                a2s[d*512 + m0 + gid + 8] = lg[1][d] + bias;
            }
        }
    }
    __syncthreads();

    // softmax over the 9 spectral taps, per column
    {
        const int n = tid;
        float v[9], mx = -1e30f;
        #pragma unroll
        for (int d = 0; d < 9; d++) { v[d] = a2s[d*512 + n]; mx = fmaxf(mx, v[d]); }
        float ssum = 0.f;
        #pragma unroll
        for (int d = 0; d < 9; d++) { v[d] = __expf(v[d] - mx); ssum += v[d]; }
        const float inv = 1.0f / ssum;
        #pragma unroll
        for (int d = 0; d < 9; d++) a2s[d*512 + n] = v[d] * inv;
    }
    cp_wait<0>();        // v band landed
    __syncthreads();

    // out += alpha * sum_d attn[d,ch] * v[ch+d-4, p]
    const float alpha = alpha_p[0];
    float* outb = out + (size_t)b * NFLAT;
    int ch = tid / 81;
    int p  = tid - ch * 81;
    for (int e = tid; e < NFLAT; e += 512) {
        float s = 0.f;
        #pragma unroll
        for (int d = 0; d < 9; d++)
            s = fmaf(a2s[d*512 + ch], vsm[(ch + d)*81 + p], s);
        outb[e] += alpha * s;
        p += 26; ch += 6;                 // advance by 512 = 6*81 + 26
        if (p >= 81) { p -= 81; ch += 1; }
    }
}

extern "C" void kernel_launch(void* const* d_in, const int* in_sizes, int n_in,
                              void* d_out, int out_size) {
    const float* x         = (const float*)d_in[0];
    const float* alpha     = (const float*)d_in[1];
    const float* sa_key_w  = (const float*)d_in[2];
    const float* sa_key_bn = (const float*)d_in[3];
    const float* sa_att_w1 = (const float*)d_in[4];
    const float* sa_att_bn = (const float*)d_in[5];
    const float* sa_att_w2 = (const float*)d_in[6];
    const float* sa_att_b2 = (const float*)d_in[7];
    const float* se_key_w  = (const float*)d_in[8];
    const float* se_key_b  = (const float*)d_in[9];
    const float* se_att_w1 = (const float*)d_in[10];
    const float* se_att_bn = (const float*)d_in[11];
    const float* se_att_w2 = (const float*)d_in[12];
    const float* se_att_b2 = (const float*)d_in[13];
    const float* se_val_w  = (const float*)d_in[14];
    const float* se_val_b  = (const float*)d_in[15];
    float* out = (float*)d_out;

    const int smemA = A_SMEM_FLOATS * 4;     // 36808 B
    const int smemB = B_SMEM_FLOATS * 4;     // 190476 B
    cudaFuncSetAttribute(dmuca_kernelA,
        cudaFuncAttributeMaxDynamicSharedMemorySize, smemA);
    cudaFuncSetAttribute(dmuca_kernelB,
        cudaFuncAttributeMaxDynamicSharedMemorySize, smemB);

    dmuca_kernelA<<<NB*8, 256, smemA>>>(x, alpha, sa_key_w, sa_key_bn,
                                        sa_att_w1, sa_att_bn, sa_att_w2, sa_att_b2,
                                        se_key_w, se_key_b, se_val_w, se_val_b, out);
    dmuca_kernelB<<<NB, 512, smemB>>>(x, alpha, se_att_w1, se_att_bn,
                                      se_att_w2, se_att_b2, out);
}

// round 15
// speedup vs baseline: 1.0931x; 1.0931x over previous
#include <cuda_runtime.h>
#include <cuda_bf16.h>
#include <cstdint>

#define NB    256
#define NC    512
#define NHW   81
#define NFLAT (NC*NHW)           // 41472 per batch
#define EPSV  1e-5f

__device__ __forceinline__ float to_tf32(float x) {
    float r; asm("cvt.rna.tf32.f32 %0, %1;" : "=f"(r) : "f"(x)); return r;
}
// m16n8k8 tf32 warp MMA (baseline PTX, sm_80+): D += A*B
__device__ __forceinline__ void mma_tf32(float c[4],
                                         uint32_t a0, uint32_t a1,
                                         uint32_t a2, uint32_t a3,
                                         uint32_t b0, uint32_t b1) {
    asm volatile("mma.sync.aligned.m16n8k8.row.col.f32.tf32.tf32.f32 "
                 "{%0,%1,%2,%3}, {%4,%5,%6,%7}, {%8,%9}, {%0,%1,%2,%3};"
                 : "+f"(c[0]), "+f"(c[1]), "+f"(c[2]), "+f"(c[3])
                 : "r"(a0), "r"(a1), "r"(a2), "r"(a3), "r"(b0), "r"(b1));
}
__device__ __forceinline__ void cp_async16(uint32_t s, const void* g) {
    asm volatile("cp.async.ca.shared.global [%0], [%1], 16;" :: "r"(s), "l"(g));
}
__device__ __forceinline__ void cp_commit() {
    asm volatile("cp.async.commit_group;");
}
template<int N>
__device__ __forceinline__ void cp_wait() {
    asm volatile("cp.async.wait_group %0;" :: "n"(N));
}

// Global scratch (allocation-free rule: __device__ arrays)
__device__ __align__(16) float g_k1[(size_t)NB * NFLAT];  // SeMCA key
__device__ __align__(16) float g_v [(size_t)NB * NFLAT];  // SeMCA value (dw3x3)

// ---------------------------------------------------------------------------
// Kernel A (banded): round-13 structure (ks/k1st smem stage, P stride 24)
// + sliding-window spectral k1: sekw[p*9+d] is channel-independent, so each
// thread computes its 8 channels' k1 as a 1-D convolution over 16 Xs rows
// (16+9 LDS instead of 72 per (thread,t)).
// smem floats: Xs[5832] | sekw[729] | sekb[81] | stage[8*1296] | P[64*24]
//   total 18546 fl = 74184 B -> 3 CTAs/SM
// ---------------------------------------------------------------------------
#define A_SMEM_FLOATS (5832 + 729 + 81 + 8*1296 + 64*24)   // 18546

__global__ __launch_bounds__(256, 3)
void dmuca_kernelA(const float* __restrict__ x,
                   const float* __restrict__ alpha_p,
                   const float* __restrict__ sa_key_w,
                   const float* __restrict__ sa_key_bn,
                   const float* __restrict__ sa_att_w1,
                   const float* __restrict__ sa_att_bn,
                   const float* __restrict__ sa_att_w2,
                   const float* __restrict__ sa_att_b2,
                   const float* __restrict__ se_key_w,
                   const float* __restrict__ se_key_b,
                   const float* __restrict__ se_val_w,
                   const float* __restrict__ se_val_b,
                   float* __restrict__ out)
{
    extern __shared__ float sm[];
    float* Xs    = sm;                    // 5832 (72 rows x 81)
    float* sekw  = sm + 5832;             // 729
    float* sekb  = sekw + 729;            // 81
    float* stage = sekb + 81;             // 8 warps * 1296 (ks | k1st)
    float* P     = stage + 8*1296;        // 64 ch * 24

    const int bb   = blockIdx.x;
    const int b    = bb >> 3;
    const int band = bb & 7;
    const int chlo = band << 6;
    const int tid  = threadIdx.x;
    const int warp = tid >> 5;
    const int lane = tid & 31;
    const float* xb = x + (size_t)b * NFLAT;

    // ---- staging ----
    {
        const int gbase = (chlo - 4) * NHW;
        for (int i = tid; i < 5832; i += 256) {
            const int g = gbase + i;
            Xs[i] = ((unsigned)g < (unsigned)NFLAT) ? xb[g] : 0.f;
        }
        for (int i = tid; i < 729; i += 256) sekw[i] = se_key_w[i];
        if (tid < 81) sekb[tid] = se_key_b[tid];

        // P per local channel c: [0..8] val_w, [9..17] key_w, [18] val_b,
        // [19] keyS, [20] keyH, [21] attS, [22] attH, [23] att_w2
        for (int i = tid; i < 576; i += 256) {        // val_w
            const int c = i / 9, k = i - c * 9;
            P[c*24 + k] = se_val_w[(chlo + c)*9 + k];
        }
        for (int i = tid; i < 576; i += 256) {        // key_w
            const int c = i / 9, k = i - c * 9;
            P[c*24 + 9 + k] = sa_key_w[(chlo + c)*9 + k];
        }
        if (tid < 64) {
            const int ch = chlo + tid;
            float* Pc = P + tid*24;
            Pc[18] = se_val_b[ch];
            const float s1 = sa_key_bn[ch] * rsqrtf(sa_key_bn[1536 + ch] + EPSV);
            Pc[19] = s1;
            Pc[20] = sa_key_bn[512 + ch] - sa_key_bn[1024 + ch] * s1;
            const float s2 = sa_att_bn[ch] * rsqrtf(sa_att_bn[1536 + ch] + EPSV);
            Pc[21] = s2;
            Pc[22] = sa_att_bn[512 + ch] - sa_att_bn[1024 + ch] * s2;
            Pc[23] = sa_att_w2[ch];
        }
    }
    __syncthreads();

    const float alpha = alpha_p[0];
    const float oma   = 1.0f - alpha;

    const int g_head = (chlo >> 3) + warp;
    const int chbase = chlo + warp * 8;
    float* ks   = stage + warp * 1296;    // k1s: 8ch x 81
    float* k1st = ks + 648;               // k1 : 8ch x 81

    // ---- Part 1a: spectral k1 via sliding window (t outer) -----------------
    // Tap cc = ch+d-4 -> Xs row lc+d; for this warp's 8 channels the rows span
    // warp*8 .. warp*8+15 (16 rows). Weight sekw[p*9+d] is channel-independent.
    {
        float* gk0 = g_k1 + (size_t)b * NFLAT + chbase * NHW;
        #pragma unroll
        for (int t = 0; t < 3; t++) {
            const int p = lane + 32 * t;
            if (p < 81) {
                float w[9];
                #pragma unroll
                for (int d = 0; d < 9; d++) w[d] = sekw[p*9 + d];
                float xw[16];
                #pragma unroll
                for (int i = 0; i < 16; i++)
                    xw[i] = Xs[(warp*8 + i)*NHW + p];
                const float bias = sekb[p];
                #pragma unroll
                for (int l = 0; l < 8; l++) {
                    float acc = bias;
                    #pragma unroll
                    for (int d = 0; d < 9; d++)
                        acc = fmaf(w[d], xw[l + d], acc);
                    gk0[l*NHW + p] = acc;
                    k1st[l*81 + p] = acc;
                }
            }
        }
    }

    // ---- Part 1b: v (dw3x3+bias) -> global; k1s -> stage --------------------
    #pragma unroll
    for (int l = 0; l < 8; l++) {
        const int ch = chbase + l;
        const int lc = warp*8 + l;
        const int lr = lc + 4;
        const float* Xc = Xs + lr * NHW;
        const float* Pc = P + lc * 24;

        float wkv[9], wks[9];
        #pragma unroll
        for (int k = 0; k < 9; k++) wkv[k] = Pc[k];
        #pragma unroll
        for (int k = 0; k < 9; k++) wks[k] = Pc[9 + k];
        const float vbias = Pc[18];
        const float s  = Pc[19];
        const float sh = Pc[20];

        float* gv = g_v + (size_t)b * NFLAT + ch * NHW;

        #pragma unroll
        for (int t = 0; t < 3; t++) {
            const int p = lane + 32 * t;
            if (p < 81) {
                const int h = p / 9, w = p - h * 9;
                float va = vbias, sa = 0.f;
                #pragma unroll
                for (int kh = 0; kh < 3; kh++) {
                    const int hh = h + kh - 1;
                    if ((unsigned)hh < 9u) {
                        #pragma unroll
                        for (int kw = 0; kw < 3; kw++) {
                            const int ww = w + kw - 1;
                            if ((unsigned)ww < 9u) {
                                const float xv = Xc[hh*9 + ww];
                                va = fmaf(wkv[kh*3+kw], xv, va);
                                sa = fmaf(wks[kh*3+kw], xv, sa);
                            }
                        }
                    }
                }
                gv[p] = va;
                ks[l*81 + p] = fmaxf(fmaf(sa, s, sh), 0.f);
            }
        }
    }
    __syncwarp();

    // ---- Part 2: head attention logits -------------------------------------
    const float bg = __ldg(sa_att_b2 + g_head);
    float a2b[3] = {bg, bg, bg};
    #pragma unroll
    for (int o = 0; o < 8; o++) {
        const int oc = chbase + o;
        const float* Pc = P + (warp*8 + o) * 24;
        float w1r[16];
        #pragma unroll
        for (int i = 0; i < 16; i++) w1r[i] = __ldg(sa_att_w1 + oc*16 + i);
        const float s2  = Pc[21];
        const float sh2 = Pc[22];
        const float w2v = Pc[23];
        #pragma unroll
        for (int t = 0; t < 3; t++) {
            const int pp = lane + 32 * t;
            if (pp < 81) {
                float aa = 0.f;
                #pragma unroll
                for (int l = 0; l < 8; l++) {
                    aa = fmaf(w1r[2*l],   ks[l*81 + pp], aa);
                    aa = fmaf(w1r[2*l+1], Xs[(warp*8 + l + 4)*NHW + pp], aa);
                }
                aa = fmaxf(fmaf(aa, s2, sh2), 0.f);
                a2b[t] = fmaf(w2v, aa, a2b[t]);
            }
        }
    }

    // ---- warp softmax over 81 pixels ---------------------------------------
    float m = -1e30f;
    #pragma unroll
    for (int t = 0; t < 3; t++) { if (lane + 32*t < 81) m = fmaxf(m, a2b[t]); }
    #pragma unroll
    for (int off = 16; off > 0; off >>= 1)
        m = fmaxf(m, __shfl_xor_sync(0xffffffffu, m, off));
    float ex[3] = {0.f, 0.f, 0.f};
    float ssum = 0.f;
    #pragma unroll
    for (int t = 0; t < 3; t++) {
        const int pp = lane + 32 * t;
        if (pp < 81) { ex[t] = __expf(a2b[t] - m); ssum += ex[t]; }
    }
    #pragma unroll
    for (int off = 16; off > 0; off >>= 1)
        ssum += __shfl_xor_sync(0xffffffffu, ssum, off);
    const float inv = 1.0f / ssum;

    // ---- out = (1-a)*(k1s + attn*x) + a*k1 (k1 from smem stage) -------------
    #pragma unroll
    for (int t = 0; t < 3; t++) {
        const int pp = lane + 32 * t;
        if (pp < 81) {
            const float att = ex[t] * inv;
            #pragma unroll
            for (int l = 0; l < 8; l++) {
                const int ch = chbase + l;
                const float o2 = ks[l*81 + pp]
                               + att * Xs[(warp*8 + l + 4)*NHW + pp];
                out[(size_t)b * NFLAT + ch*NHW + pp]
                    = oma * o2 + alpha * k1st[l*81 + pp];
            }
        }
    }
}

// ---------------------------------------------------------------------------
// Kernel B (warp-MMA tf32): round-14 version (one barrier per chunk +
// overlapped v-band staging). Unchanged.
// ---------------------------------------------------------------------------
#define FB_SH   0
#define FB_W1F  16640
#define FB_A2S  42120
#define FB_W2   46728
#define FB_BNS  47457
#define FB_BNH  47538
#define B_SMEM_FLOATS 47619
#define SH_STRIDE 520

__global__ __launch_bounds__(512, 1)
void dmuca_kernelB(const float* __restrict__ x,
                   const float* __restrict__ alpha_p,
                   const float* __restrict__ se_att_w1,
                   const float* __restrict__ se_att_bn,
                   const float* __restrict__ se_att_w2,
                   const float* __restrict__ se_att_b2,
                   float* __restrict__ out)
{
    extern __shared__ float sm[];
    float* SH2 = sm + FB_SH;    // 2 x [16][520] raw f32 chunks of S
    float* W1f = sm + FB_W1F;   // [j=176][o pad 104] tf32
    float* vsm = sm;            // epilogue alias, 520*81 = 42120
    float* a2s = sm + FB_A2S;
    float* w2s = sm + FB_W2;
    float* bnS = sm + FB_BNS;
    float* bnH = sm + FB_BNH;

    const int b    = blockIdx.x;
    const int tid  = threadIdx.x;
    const int warp = tid >> 5;
    const int lane = tid & 31;
    const int gid  = lane >> 2;       // 0..7
    const int tig  = lane & 3;        // 0..3
    const float* xb  = x    + (size_t)b * NFLAT;
    const float* k1b = g_k1 + (size_t)b * NFLAT;

    const uint32_t sh_base  = (uint32_t)__cvta_generic_to_shared(SH2);
    const uint32_t vsm_base = (uint32_t)__cvta_generic_to_shared(vsm);

    // one-time staging: W1f (tf32, zero-padded), w2s, bn scale/shift
    for (int i = tid; i < 176*104; i += 512) {
        const int k = i / 104, o = i - k * 104;
        const float w = (o < 81 && k < 162) ? __ldg(se_att_w1 + o*162 + k) : 0.f;
        W1f[i] = to_tf32(w);
    }
    for (int i = tid; i < 729; i += 512) w2s[i] = se_att_w2[i];
    if (tid < 81) {
        const float gam = se_att_bn[tid],       bet = se_att_bn[81 + tid];
        const float mea = se_att_bn[162 + tid], var = se_att_bn[243 + tid];
        const float s = gam * rsqrtf(var + EPSV);
        bnS[tid] = s; bnH[tid] = bet - mea * s;
    }

    // stage chunk c (k rows c*16..c*16+15) into buffer `buf` via cp.async
    auto stage_chunk = [&](int c, int buf) {
        const uint32_t boff = (uint32_t)(buf * 16 * SH_STRIDE * 4);
        #pragma unroll
        for (int q = 0; q < 4; q++) {
            const int f4 = q * 512 + tid;          // 0..2047
            const int kk = f4 >> 7, c4 = f4 & 127; // 128 float4 per 512-f row
            const int j  = c * 16 + kk;
            const uint32_t dst = sh_base + boff
                               + (uint32_t)((kk * SH_STRIDE + c4 * 4) * 4);
            if (j < 81) {
                cp_async16(dst, (const void*)(xb + j*512 + c4*4));
            } else if (j < 162) {
                cp_async16(dst, (const void*)(k1b + (j-81)*512 + c4*4));
            } else {
                float4 z = {0.f, 0.f, 0.f, 0.f};
                *(float4*)(SH2 + buf*16*SH_STRIDE + kk*SH_STRIDE + c4*4) = z;
            }
        }
        cp_commit();
    };

    stage_chunk(0, 0);

    for (int pass = 0; pass < 2; pass++) {
        const int m0 = (warp + 16 * pass) << 4;    // channel base

        float acc[11][4];
        #pragma unroll
        for (int nb = 0; nb < 11; nb++)
            #pragma unroll
            for (int e = 0; e < 4; e++) acc[nb][e] = 0.f;

        for (int kc = 0; kc < 11; kc++) {
            const int gi = pass * 11 + kc;
            cp_wait<0>();            // chunk gi has landed
            __syncthreads();         // + all compute of chunk gi-1 done
            if (gi < 21) stage_chunk((gi + 1) % 11, (gi + 1) & 1);

            const float* sb = SH2 + (gi & 1) * 16 * SH_STRIDE;
            #pragma unroll
            for (int ks = 0; ks < 2; ks++) {
                const int kl = ks * 8 + tig;
                const int jr = kc * 16 + kl;
                const uint32_t a0 = __float_as_uint(sb[ kl     *SH_STRIDE + m0 + gid]);
                const uint32_t a1 = __float_as_uint(sb[ kl     *SH_STRIDE + m0 + gid + 8]);
                const uint32_t a2 = __float_as_uint(sb[(kl + 4)*SH_STRIDE + m0 + gid]);
                const uint32_t a3 = __float_as_uint(sb[(kl + 4)*SH_STRIDE + m0 + gid + 8]);
                const float* wr0 = W1f + (size_t)jr * 104;
                const float* wr1 = W1f + (size_t)(jr + 4) * 104;
                #pragma unroll
                for (int nb = 0; nb < 11; nb++) {
                    const uint32_t b0 = __float_as_uint(wr0[nb*8 + gid]);
                    const uint32_t b1 = __float_as_uint(wr1[nb*8 + gid]);
                    mma_tf32(acc[nb], a0, a1, a2, a3, b0, b1);
                }
            }
        }

        // After the FINAL mainloop chunk SH2/W1f are dead: overlap the v-band
        // staging (cp.async into the alias region) with the register epilogue
        // and softmax. Sync first: other warps must finish the last chunk.
        if (pass == 1) {
            __syncthreads();
            const float* vb = g_v + (size_t)b * NFLAT;
            // zero edges: rows 0..3 (first 324 floats) and 516..519 (last 324)
            for (int i = tid; i < 324; i += 512) {
                vsm[i] = 0.f;
                vsm[41796 + i] = 0.f;   // 516*81 = 41796
            }
            // interior: channels 0..511 -> vsm offset 324 + ch*81
            #pragma unroll
            for (int q = 0; q < 21; q++) {
                const int f4 = q * 512 + tid;       // float4 index
                if (f4 < 10368) {                   // 41472/4
                    cp_async16(vsm_base + (uint32_t)((324 + f4*4) * 4),
                               (const void*)(vb + f4*4));
                }
            }
            cp_commit();
        }

        // register epilogue: bn+relu+w2 -> logits for channels m0+gid, m0+gid+8
        float lg[2][9];
        #pragma unroll
        for (int rr = 0; rr < 2; rr++)
            #pragma unroll
            for (int d = 0; d < 9; d++) lg[rr][d] = 0.f;
        #pragma unroll
        for (int nb = 0; nb < 11; nb++) {
            #pragma unroll
            for (int e = 0; e < 4; e++) {
                const int o = nb*8 + tig*2 + (e & 1);
                if (o < 81) {
                    const float a1v = fmaxf(fmaf(acc[nb][e], bnS[o], bnH[o]), 0.f);
                    const int rr = e >> 1;
                    #pragma unroll
                    for (int d = 0; d < 9; d++)
                        lg[rr][d] = fmaf(w2s[d*81 + o], a1v, lg[rr][d]);
                }
            }
        }
        #pragma unroll
        for (int rr = 0; rr < 2; rr++)
            #pragma unroll
            for (int d = 0; d < 9; d++) {
                lg[rr][d] += __shfl_xor_sync(0xffffffffu, lg[rr][d], 1);
                lg[rr][d] += __shfl_xor_sync(0xffffffffu, lg[rr][d], 2);
            }
        if (tig == 0) {
            #pragma unroll
            for (int d = 0; d < 9; d++) {
                const float bias = __ldg(se_att_b2 + d);
                a2s[d*512 + m0 + gid]     = lg[0][d] + bias;
                a2s[d*512 + m0 + gid + 8] = lg[1][d] + bias;
            }
        }
    }
    __syncthreads();

    // softmax over the 9 spectral taps, per column
    {
        const int n = tid;
        float v[9], mx = -1e30f;
        #pragma unroll
        for (int d = 0; d < 9; d++) { v[d] = a2s[d*512 + n]; mx = fmaxf(mx, v[d]); }
        float ssum = 0.f;
        #pragma unroll
        for (int d = 0; d < 9; d++) { v[d] = __expf(v[d] - mx); ssum += v[d]; }
        const float inv = 1.0f / ssum;
        #pragma unroll
        for (int d = 0; d < 9; d++) a2s[d*512 + n] = v[d] * inv;
    }
    cp_wait<0>();        // v band landed
    __syncthreads();

    // out += alpha * sum_d attn[d,ch] * v[ch+d-4, p]
    const float alpha = alpha_p[0];
    float* outb = out + (size_t)b * NFLAT;
    int ch = tid / 81;
    int p  = tid - ch * 81;
    for (int e = tid; e < NFLAT; e += 512) {
        float s = 0.f;
        #pragma unroll
        for (int d = 0; d < 9; d++)
            s = fmaf(a2s[d*512 + ch], vsm[(ch + d)*81 + p], s);
        outb[e] += alpha * s;
        p += 26; ch += 6;                 // advance by 512 = 6*81 + 26
        if (p >= 81) { p -= 81; ch += 1; }
    }
}

extern "C" void kernel_launch(void* const* d_in, const int* in_sizes, int n_in,
                              void* d_out, int out_size) {
    const float* x         = (const float*)d_in[0];
    const float* alpha     = (const float*)d_in[1];
    const float* sa_key_w  = (const float*)d_in[2];
    const float* sa_key_bn = (const float*)d_in[3];
    const float* sa_att_w1 = (const float*)d_in[4];
    const float* sa_att_bn = (const float*)d_in[5];
    const float* sa_att_w2 = (const float*)d_in[6];
    const float* sa_att_b2 = (const float*)d_in[7];
    const float* se_key_w  = (const float*)d_in[8];
    const float* se_key_b  = (const float*)d_in[9];
    const float* se_att_w1 = (const float*)d_in[10];
    const float* se_att_bn = (const float*)d_in[11];
    const float* se_att_w2 = (const float*)d_in[12];
    const float* se_att_b2 = (const float*)d_in[13];
    const float* se_val_w  = (const float*)d_in[14];
    const float* se_val_b  = (const float*)d_in[15];
    float* out = (float*)d_out;

    const int smemA = A_SMEM_FLOATS * 4;     // 74184 B
    const int smemB = B_SMEM_FLOATS * 4;     // 190476 B
    cudaFuncSetAttribute(dmuca_kernelA,
        cudaFuncAttributeMaxDynamicSharedMemorySize, smemA);
    cudaFuncSetAttribute(dmuca_kernelB,
        cudaFuncAttributeMaxDynamicSharedMemorySize, smemB);

    dmuca_kernelA<<<NB*8, 256, smemA>>>(x, alpha, sa_key_w, sa_key_bn,
                                        sa_att_w1, sa_att_bn, sa_att_w2, sa_att_b2,
                                        se_key_w, se_key_b, se_val_w, se_val_b, out);
    dmuca_kernelB<<<NB, 512, smemB>>>(x, alpha, se_att_w1, se_att_bn,
                                      se_att_w2, se_att_b2, out);
}

// round 16
// speedup vs baseline: 1.2421x; 1.1364x over previous
#include <cuda_runtime.h>
#include <cuda_bf16.h>
#include <cstdint>

#define NB    256
#define NC    512
#define NHW   81
#define NFLAT (NC*NHW)           // 41472 per batch
#define EPSV  1e-5f

__device__ __forceinline__ float to_tf32(float x) {
    float r; asm("cvt.rna.tf32.f32 %0, %1;" : "=f"(r) : "f"(x)); return r;
}
// m16n8k8 tf32 warp MMA (baseline PTX, sm_80+): D += A*B
__device__ __forceinline__ void mma_tf32(float c[4],
                                         uint32_t a0, uint32_t a1,
                                         uint32_t a2, uint32_t a3,
                                         uint32_t b0, uint32_t b1) {
    asm volatile("mma.sync.aligned.m16n8k8.row.col.f32.tf32.tf32.f32 "
                 "{%0,%1,%2,%3}, {%4,%5,%6,%7}, {%8,%9}, {%0,%1,%2,%3};"
                 : "+f"(c[0]), "+f"(c[1]), "+f"(c[2]), "+f"(c[3])
                 : "r"(a0), "r"(a1), "r"(a2), "r"(a3), "r"(b0), "r"(b1));
}
__device__ __forceinline__ void cp_async16(uint32_t s, const void* g) {
    asm volatile("cp.async.ca.shared.global [%0], [%1], 16;" :: "r"(s), "l"(g));
}
__device__ __forceinline__ void cp_commit() {
    asm volatile("cp.async.commit_group;");
}
template<int N>
__device__ __forceinline__ void cp_wait() {
    asm volatile("cp.async.wait_group %0;" :: "n"(N));
}

// Global scratch (allocation-free rule: __device__ arrays)
__device__ __align__(16) float g_k1[(size_t)NB * NFLAT];  // SeMCA key
__device__ __align__(16) float g_v [(size_t)NB * NFLAT];  // SeMCA value (dw3x3)

// ---------------------------------------------------------------------------
// Kernel A (banded, sliding-window k1): unchanged from round 15.
// smem floats: Xs[5832] | sekw[729] | sekb[81] | stage[8*1296] | P[64*24]
// ---------------------------------------------------------------------------
#define A_SMEM_FLOATS (5832 + 729 + 81 + 8*1296 + 64*24)   // 18546

__global__ __launch_bounds__(256, 3)
void dmuca_kernelA(const float* __restrict__ x,
                   const float* __restrict__ alpha_p,
                   const float* __restrict__ sa_key_w,
                   const float* __restrict__ sa_key_bn,
                   const float* __restrict__ sa_att_w1,
                   const float* __restrict__ sa_att_bn,
                   const float* __restrict__ sa_att_w2,
                   const float* __restrict__ sa_att_b2,
                   const float* __restrict__ se_key_w,
                   const float* __restrict__ se_key_b,
                   const float* __restrict__ se_val_w,
                   const float* __restrict__ se_val_b,
                   float* __restrict__ out)
{
    extern __shared__ float sm[];
    float* Xs    = sm;                    // 5832 (72 rows x 81)
    float* sekw  = sm + 5832;             // 729
    float* sekb  = sekw + 729;            // 81
    float* stage = sekb + 81;             // 8 warps * 1296 (ks | k1st)
    float* P     = stage + 8*1296;        // 64 ch * 24

    const int bb   = blockIdx.x;
    const int b    = bb >> 3;
    const int band = bb & 7;
    const int chlo = band << 6;
    const int tid  = threadIdx.x;
    const int warp = tid >> 5;
    const int lane = tid & 31;
    const float* xb = x + (size_t)b * NFLAT;

    {
        const int gbase = (chlo - 4) * NHW;
        for (int i = tid; i < 5832; i += 256) {
            const int g = gbase + i;
            Xs[i] = ((unsigned)g < (unsigned)NFLAT) ? xb[g] : 0.f;
        }
        for (int i = tid; i < 729; i += 256) sekw[i] = se_key_w[i];
        if (tid < 81) sekb[tid] = se_key_b[tid];

        for (int i = tid; i < 576; i += 256) {        // val_w
            const int c = i / 9, k = i - c * 9;
            P[c*24 + k] = se_val_w[(chlo + c)*9 + k];
        }
        for (int i = tid; i < 576; i += 256) {        // key_w
            const int c = i / 9, k = i - c * 9;
            P[c*24 + 9 + k] = sa_key_w[(chlo + c)*9 + k];
        }
        if (tid < 64) {
            const int ch = chlo + tid;
            float* Pc = P + tid*24;
            Pc[18] = se_val_b[ch];
            const float s1 = sa_key_bn[ch] * rsqrtf(sa_key_bn[1536 + ch] + EPSV);
            Pc[19] = s1;
            Pc[20] = sa_key_bn[512 + ch] - sa_key_bn[1024 + ch] * s1;
            const float s2 = sa_att_bn[ch] * rsqrtf(sa_att_bn[1536 + ch] + EPSV);
            Pc[21] = s2;
            Pc[22] = sa_att_bn[512 + ch] - sa_att_bn[1024 + ch] * s2;
            Pc[23] = sa_att_w2[ch];
        }
    }
    __syncthreads();

    const float alpha = alpha_p[0];
    const float oma   = 1.0f - alpha;

    const int g_head = (chlo >> 3) + warp;
    const int chbase = chlo + warp * 8;
    float* ks   = stage + warp * 1296;    // k1s: 8ch x 81
    float* k1st = ks + 648;               // k1 : 8ch x 81

    // Part 1a: spectral k1 via sliding window (weights channel-independent)
    {
        float* gk0 = g_k1 + (size_t)b * NFLAT + chbase * NHW;
        #pragma unroll
        for (int t = 0; t < 3; t++) {
            const int p = lane + 32 * t;
            if (p < 81) {
                float w[9];
                #pragma unroll
                for (int d = 0; d < 9; d++) w[d] = sekw[p*9 + d];
                float xw[16];
                #pragma unroll
                for (int i = 0; i < 16; i++)
                    xw[i] = Xs[(warp*8 + i)*NHW + p];
                const float bias = sekb[p];
                #pragma unroll
                for (int l = 0; l < 8; l++) {
                    float acc = bias;
                    #pragma unroll
                    for (int d = 0; d < 9; d++)
                        acc = fmaf(w[d], xw[l + d], acc);
                    gk0[l*NHW + p] = acc;
                    k1st[l*81 + p] = acc;
                }
            }
        }
    }

    // Part 1b: v (dw3x3+bias) -> global; k1s -> stage
    #pragma unroll
    for (int l = 0; l < 8; l++) {
        const int ch = chbase + l;
        const int lc = warp*8 + l;
        const int lr = lc + 4;
        const float* Xc = Xs + lr * NHW;
        const float* Pc = P + lc * 24;

        float wkv[9], wks[9];
        #pragma unroll
        for (int k = 0; k < 9; k++) wkv[k] = Pc[k];
        #pragma unroll
        for (int k = 0; k < 9; k++) wks[k] = Pc[9 + k];
        const float vbias = Pc[18];
        const float s  = Pc[19];
        const float sh = Pc[20];

        float* gv = g_v + (size_t)b * NFLAT + ch * NHW;

        #pragma unroll
        for (int t = 0; t < 3; t++) {
            const int p = lane + 32 * t;
            if (p < 81) {
                const int h = p / 9, w = p - h * 9;
                float va = vbias, sa = 0.f;
                #pragma unroll
                for (int kh = 0; kh < 3; kh++) {
                    const int hh = h + kh - 1;
                    if ((unsigned)hh < 9u) {
                        #pragma unroll
                        for (int kw = 0; kw < 3; kw++) {
                            const int ww = w + kw - 1;
                            if ((unsigned)ww < 9u) {
                                const float xv = Xc[hh*9 + ww];
                                va = fmaf(wkv[kh*3+kw], xv, va);
                                sa = fmaf(wks[kh*3+kw], xv, sa);
                            }
                        }
                    }
                }
                gv[p] = va;
                ks[l*81 + p] = fmaxf(fmaf(sa, s, sh), 0.f);
            }
        }
    }
    __syncwarp();

    // Part 2: head attention logits
    const float bg = __ldg(sa_att_b2 + g_head);
    float a2b[3] = {bg, bg, bg};
    #pragma unroll
    for (int o = 0; o < 8; o++) {
        const int oc = chbase + o;
        const float* Pc = P + (warp*8 + o) * 24;
        float w1r[16];
        #pragma unroll
        for (int i = 0; i < 16; i++) w1r[i] = __ldg(sa_att_w1 + oc*16 + i);
        const float s2  = Pc[21];
        const float sh2 = Pc[22];
        const float w2v = Pc[23];
        #pragma unroll
        for (int t = 0; t < 3; t++) {
            const int pp = lane + 32 * t;
            if (pp < 81) {
                float aa = 0.f;
                #pragma unroll
                for (int l = 0; l < 8; l++) {
                    aa = fmaf(w1r[2*l],   ks[l*81 + pp], aa);
                    aa = fmaf(w1r[2*l+1], Xs[(warp*8 + l + 4)*NHW + pp], aa);
                }
                aa = fmaxf(fmaf(aa, s2, sh2), 0.f);
                a2b[t] = fmaf(w2v, aa, a2b[t]);
            }
        }
    }

    // warp softmax over 81 pixels
    float m = -1e30f;
    #pragma unroll
    for (int t = 0; t < 3; t++) { if (lane + 32*t < 81) m = fmaxf(m, a2b[t]); }
    #pragma unroll
    for (int off = 16; off > 0; off >>= 1)
        m = fmaxf(m, __shfl_xor_sync(0xffffffffu, m, off));
    float ex[3] = {0.f, 0.f, 0.f};
    float ssum = 0.f;
    #pragma unroll
    for (int t = 0; t < 3; t++) {
        const int pp = lane + 32 * t;
        if (pp < 81) { ex[t] = __expf(a2b[t] - m); ssum += ex[t]; }
    }
    #pragma unroll
    for (int off = 16; off > 0; off >>= 1)
        ssum += __shfl_xor_sync(0xffffffffu, ssum, off);
    const float inv = 1.0f / ssum;

    // out = (1-a)*(k1s + attn*x) + a*k1
    #pragma unroll
    for (int t = 0; t < 3; t++) {
        const int pp = lane + 32 * t;
        if (pp < 81) {
            const float att = ex[t] * inv;
            #pragma unroll
            for (int l = 0; l < 8; l++) {
                const int ch = chbase + l;
                const float o2 = ks[l*81 + pp]
                               + att * Xs[(warp*8 + l + 4)*NHW + pp];
                out[(size_t)b * NFLAT + ch*NHW + pp]
                    = oma * o2 + alpha * k1st[l*81 + pp];
            }
        }
    }
}

// ---------------------------------------------------------------------------
// Kernel B (warp-MMA tf32, 1024 threads, SINGLE m-pass): grid = NB.
// 32 warps; warp w owns channels [w*16, w*16+16) x all 88 o-cols. S staged
// once (11 chunks, double-buffered cp.async, one barrier per chunk). v-band
// staging overlapped with the register epilogue. Softmax + combine as before.
// smem layout identical to rounds 11-15 (190476 B).
// ---------------------------------------------------------------------------
#define FB_SH   0
#define FB_W1F  16640
#define FB_A2S  42120
#define FB_W2   46728
#define FB_BNS  47457
#define FB_BNH  47538
#define B_SMEM_FLOATS 47619
#define SH_STRIDE 520

__global__ __launch_bounds__(1024, 1)
void dmuca_kernelB(const float* __restrict__ x,
                   const float* __restrict__ alpha_p,
                   const float* __restrict__ se_att_w1,
                   const float* __restrict__ se_att_bn,
                   const float* __restrict__ se_att_w2,
                   const float* __restrict__ se_att_b2,
                   float* __restrict__ out)
{
    extern __shared__ float sm[];
    float* SH2 = sm + FB_SH;    // 2 x [16][520] raw f32 chunks of S
    float* W1f = sm + FB_W1F;   // [j=176][o pad 104] tf32
    float* vsm = sm;            // epilogue alias, 520*81 = 42120
    float* a2s = sm + FB_A2S;
    float* w2s = sm + FB_W2;
    float* bnS = sm + FB_BNS;
    float* bnH = sm + FB_BNH;

    const int b    = blockIdx.x;
    const int tid  = threadIdx.x;
    const int warp = tid >> 5;        // 0..31
    const int lane = tid & 31;
    const int gid  = lane >> 2;       // 0..7
    const int tig  = lane & 3;        // 0..3
    const float* xb  = x    + (size_t)b * NFLAT;
    const float* k1b = g_k1 + (size_t)b * NFLAT;

    const uint32_t sh_base  = (uint32_t)__cvta_generic_to_shared(SH2);
    const uint32_t vsm_base = (uint32_t)__cvta_generic_to_shared(vsm);

    // one-time staging: W1f (tf32, zero-padded), w2s, bn scale/shift
    for (int i = tid; i < 176*104; i += 1024) {
        const int k = i / 104, o = i - k * 104;
        const float w = (o < 81 && k < 162) ? __ldg(se_att_w1 + o*162 + k) : 0.f;
        W1f[i] = to_tf32(w);
    }
    for (int i = tid; i < 729; i += 1024) w2s[i] = se_att_w2[i];
    if (tid < 81) {
        const float gam = se_att_bn[tid],       bet = se_att_bn[81 + tid];
        const float mea = se_att_bn[162 + tid], var = se_att_bn[243 + tid];
        const float s = gam * rsqrtf(var + EPSV);
        bnS[tid] = s; bnH[tid] = bet - mea * s;
    }

    // stage chunk c (k rows c*16..c*16+15) into buffer `buf` via cp.async
    auto stage_chunk = [&](int c, int buf) {
        const uint32_t boff = (uint32_t)(buf * 16 * SH_STRIDE * 4);
        #pragma unroll
        for (int q = 0; q < 2; q++) {
            const int f4 = q * 1024 + tid;         // 0..2047
            const int kk = f4 >> 7, c4 = f4 & 127; // 128 float4 per 512-f row
            const int j  = c * 16 + kk;
            const uint32_t dst = sh_base + boff
                               + (uint32_t)((kk * SH_STRIDE + c4 * 4) * 4);
            if (j < 81) {
                cp_async16(dst, (const void*)(xb + j*512 + c4*4));
            } else if (j < 162) {
                cp_async16(dst, (const void*)(k1b + (j-81)*512 + c4*4));
            } else {
                float4 z = {0.f, 0.f, 0.f, 0.f};
                *(float4*)(SH2 + buf*16*SH_STRIDE + kk*SH_STRIDE + c4*4) = z;
            }
        }
        cp_commit();
    };

    stage_chunk(0, 0);

    const int m0 = warp << 4;          // channel base: warp*16, 0..496

    float acc[11][4];
    #pragma unroll
    for (int nb = 0; nb < 11; nb++)
        #pragma unroll
        for (int e = 0; e < 4; e++) acc[nb][e] = 0.f;

    for (int kc = 0; kc < 11; kc++) {
        cp_wait<0>();            // chunk kc has landed
        __syncthreads();         // + all compute of chunk kc-1 done
        if (kc < 10) stage_chunk(kc + 1, (kc + 1) & 1);

        const float* sb = SH2 + (kc & 1) * 16 * SH_STRIDE;
        #pragma unroll
        for (int ks = 0; ks < 2; ks++) {
            const int kl = ks * 8 + tig;
            const int jr = kc * 16 + kl;
            const uint32_t a0 = __float_as_uint(sb[ kl     *SH_STRIDE + m0 + gid]);
            const uint32_t a1 = __float_as_uint(sb[ kl     *SH_STRIDE + m0 + gid + 8]);
            const uint32_t a2 = __float_as_uint(sb[(kl + 4)*SH_STRIDE + m0 + gid]);
            const uint32_t a3 = __float_as_uint(sb[(kl + 4)*SH_STRIDE + m0 + gid + 8]);
            const float* wr0 = W1f + (size_t)jr * 104;
            const float* wr1 = W1f + (size_t)(jr + 4) * 104;
            #pragma unroll
            for (int nb = 0; nb < 11; nb++) {
                const uint32_t b0 = __float_as_uint(wr0[nb*8 + gid]);
                const uint32_t b1 = __float_as_uint(wr1[nb*8 + gid]);
                mma_tf32(acc[nb], a0, a1, a2, a3, b0, b1);
            }
        }
    }

    // Mainloop done; SH2/W1f dead after this sync. Overlap the v-band staging
    // (cp.async into the alias region) with the register epilogue + softmax.
    __syncthreads();
    {
        const float* vb = g_v + (size_t)b * NFLAT;
        // zero edges: rows 0..3 (first 324 floats) and 516..519 (last 324)
        for (int i = tid; i < 324; i += 1024) {
            vsm[i] = 0.f;
            vsm[41796 + i] = 0.f;   // 516*81 = 41796
        }
        // interior: channels 0..511 -> vsm offset 324 + ch*81
        #pragma unroll
        for (int q = 0; q < 11; q++) {
            const int f4 = q * 1024 + tid;      // float4 index
            if (f4 < 10368) {                   // 41472/4
                cp_async16(vsm_base + (uint32_t)((324 + f4*4) * 4),
                           (const void*)(vb + f4*4));
            }
        }
        cp_commit();
    }

    // register epilogue: bn+relu+w2 -> logits for channels m0+gid, m0+gid+8
    {
        float lg[2][9];
        #pragma unroll
        for (int rr = 0; rr < 2; rr++)
            #pragma unroll
            for (int d = 0; d < 9; d++) lg[rr][d] = 0.f;
        #pragma unroll
        for (int nb = 0; nb < 11; nb++) {
            #pragma unroll
            for (int e = 0; e < 4; e++) {
                const int o = nb*8 + tig*2 + (e & 1);
                if (o < 81) {
                    const float a1v = fmaxf(fmaf(acc[nb][e], bnS[o], bnH[o]), 0.f);
                    const int rr = e >> 1;
                    #pragma unroll
                    for (int d = 0; d < 9; d++)
                        lg[rr][d] = fmaf(w2s[d*81 + o], a1v, lg[rr][d]);
                }
            }
        }
        #pragma unroll
        for (int rr = 0; rr < 2; rr++)
            #pragma unroll
            for (int d = 0; d < 9; d++) {
                lg[rr][d] += __shfl_xor_sync(0xffffffffu, lg[rr][d], 1);
                lg[rr][d] += __shfl_xor_sync(0xffffffffu, lg[rr][d], 2);
            }
        if (tig == 0) {
            #pragma unroll
            for (int d = 0; d < 9; d++) {
                const float bias = __ldg(se_att_b2 + d);
                a2s[d*512 + m0 + gid]     = lg[0][d] + bias;
                a2s[d*512 + m0 + gid + 8] = lg[1][d] + bias;
            }
        }
    }
    __syncthreads();

    // softmax over the 9 spectral taps, per column (threads 0..511)
    if (tid < 512) {
        const int n = tid;
        float v[9], mx = -1e30f;
        #pragma unroll
        for (int d = 0; d < 9; d++) { v[d] = a2s[d*512 + n]; mx = fmaxf(mx, v[d]); }
        float ssum = 0.f;
        #pragma unroll
        for (int d = 0; d < 9; d++) { v[d] = __expf(v[d] - mx); ssum += v[d]; }
        const float inv = 1.0f / ssum;
        #pragma unroll
        for (int d = 0; d < 9; d++) a2s[d*512 + n] = v[d] * inv;
    }
    cp_wait<0>();        // v band landed
    __syncthreads();

    // out += alpha * sum_d attn[d,ch] * v[ch+d-4, p]
    const float alpha = alpha_p[0];
    float* outb = out + (size_t)b * NFLAT;
    int ch = tid / 81;
    int p  = tid - ch * 81;
    for (int e = tid; e < NFLAT; e += 1024) {
        float s = 0.f;
        #pragma unroll
        for (int d = 0; d < 9; d++)
            s = fmaf(a2s[d*512 + ch], vsm[(ch + d)*81 + p], s);
        outb[e] += alpha * s;
        p += 52; ch += 12;                // advance by 1024 = 12*81 + 52
        if (p >= 81) { p -= 81; ch += 1; }
    }
}

extern "C" void kernel_launch(void* const* d_in, const int* in_sizes, int n_in,
                              void* d_out, int out_size) {
    const float* x         = (const float*)d_in[0];
    const float* alpha     = (const float*)d_in[1];
    const float* sa_key_w  = (const float*)d_in[2];
    const float* sa_key_bn = (const float*)d_in[3];
    const float* sa_att_w1 = (const float*)d_in[4];
    const float* sa_att_bn = (const float*)d_in[5];
    const float* sa_att_w2 = (const float*)d_in[6];
    const float* sa_att_b2 = (const float*)d_in[7];
    const float* se_key_w  = (const float*)d_in[8];
    const float* se_key_b  = (const float*)d_in[9];
    const float* se_att_w1 = (const float*)d_in[10];
    const float* se_att_bn = (const float*)d_in[11];
    const float* se_att_w2 = (const float*)d_in[12];
    const float* se_att_b2 = (const float*)d_in[13];
    const float* se_val_w  = (const float*)d_in[14];
    const float* se_val_b  = (const float*)d_in[15];
    float* out = (float*)d_out;

    const int smemA = A_SMEM_FLOATS * 4;     // 74184 B
    const int smemB = B_SMEM_FLOATS * 4;     // 190476 B
    cudaFuncSetAttribute(dmuca_kernelA,
        cudaFuncAttributeMaxDynamicSharedMemorySize, smemA);
    cudaFuncSetAttribute(dmuca_kernelB,
        cudaFuncAttributeMaxDynamicSharedMemorySize, smemB);

    dmuca_kernelA<<<NB*8, 256, smemA>>>(x, alpha, sa_key_w, sa_key_bn,
                                        sa_att_w1, sa_att_bn, sa_att_w2, sa_att_b2,
                                        se_key_w, se_key_b, se_val_w, se_val_b, out);
    dmuca_kernelB<<<NB, 1024, smemB>>>(x, alpha, se_att_w1, se_att_bn,
                                       se_att_w2, se_att_b2, out);
}